// round 11
// baseline (speedup 1.0000x reference)
#include <cuda_runtime.h>
#include <cuda_bf16.h>
#include <math.h>
#include <stddef.h>
#include <stdint.h>

#define D_MODEL 1024
#define DK      1024
#define BATCH   4
#define SEQ     2048
#define BT      (BATCH * SEQ)

typedef __nv_bfloat16 bf16;
typedef uint8_t fp8;

// scales: hi8 = hi/8, lo8 = 8*lo -> product scale 1
#define S_HI8 0.125f
#define S_LO8 8.0f

__device__ bf16 g_xhi [(size_t)BT * D_MODEL];
__device__ fp8  g_xhi8[(size_t)BT * D_MODEL];
__device__ fp8  g_xlo8[(size_t)BT * D_MODEL];
__device__ bf16 g_wthi [3][(size_t)D_MODEL * DK];   // (32W)^T
__device__ fp8  g_wthi8[3][(size_t)D_MODEL * DK];
__device__ fp8  g_wtlo8[3][(size_t)D_MODEL * DK];
__device__ bf16 g_QKVhi [3][(size_t)BT * DK];       // 32*Q, 32*K, 32*V
__device__ bf16 g_QKVlo [3][(size_t)BT * DK];
__device__ fp8  g_QKVhi8[3][(size_t)BT * DK];
__device__ fp8  g_QKVlo8[3][(size_t)BT * DK];
__device__ bf16 g_Vthi[(size_t)BATCH * DK * SEQ];
__device__ bf16 g_Vtlo[(size_t)BATCH * DK * SEQ];
__device__ float g_S[(size_t)BATCH * SEQ * SEQ];
__device__ bf16 g_Phi[(size_t)BATCH * SEQ * SEQ];
__device__ bf16 g_Plo[(size_t)BATCH * SEQ * SEQ];

__device__ __forceinline__ void split_f32(float v, bf16& h, bf16& l) {
    h = __float2bfloat16(v);
    l = __float2bfloat16(v - __bfloat162float(h));
}
__device__ __forceinline__ uint32_t smem_to_u32(const void* p) {
    uint32_t a;
    asm("{ .reg .u64 t; cvta.to.shared.u64 t, %1; cvt.u32.u64 %0, t; }" : "=r"(a) : "l"(p));
    return a;
}
__device__ __forceinline__ void ldm_x4(uint32_t& r0, uint32_t& r1, uint32_t& r2, uint32_t& r3,
                                       uint32_t addr) {
    asm volatile("ldmatrix.sync.aligned.m8n8.x4.shared.b16 {%0,%1,%2,%3}, [%4];"
                 : "=r"(r0), "=r"(r1), "=r"(r2), "=r"(r3) : "r"(addr));
}
__device__ __forceinline__ void mma_bf16(float* c, const uint32_t* a, const uint32_t* b) {
    asm volatile("mma.sync.aligned.m16n8k16.row.col.f32.bf16.bf16.f32 "
                 "{%0,%1,%2,%3}, {%4,%5,%6,%7}, {%8,%9}, {%0,%1,%2,%3};"
                 : "+f"(c[0]), "+f"(c[1]), "+f"(c[2]), "+f"(c[3])
                 : "r"(a[0]), "r"(a[1]), "r"(a[2]), "r"(a[3]), "r"(b[0]), "r"(b[1]));
}
__device__ __forceinline__ void mma_fp8(float* c, const uint32_t* a, const uint32_t* b) {
    asm volatile("mma.sync.aligned.m16n8k32.row.col.f32.e4m3.e4m3.f32 "
                 "{%0,%1,%2,%3}, {%4,%5,%6,%7}, {%8,%9}, {%0,%1,%2,%3};"
                 : "+f"(c[0]), "+f"(c[1]), "+f"(c[2]), "+f"(c[3])
                 : "r"(a[0]), "r"(a[1]), "r"(a[2]), "r"(a[3]), "r"(b[0]), "r"(b[1]));
}
__device__ __forceinline__ unsigned short pack2_e4m3(float f0, float f1) {
    unsigned short r;
    asm("cvt.rn.satfinite.e4m3x2.f32 %0, %1, %2;" : "=h"(r) : "f"(f1), "f"(f0));
    return r;
}
__device__ __forceinline__ uint32_t pack4_e4m3(float f0, float f1, float f2, float f3) {
    return (uint32_t)pack2_e4m3(f0, f1) | ((uint32_t)pack2_e4m3(f2, f3) << 16);
}

#define CP_ASYNC16(dst, src) \
    asm volatile("cp.async.cg.shared.global [%0], [%1], 16;" :: "r"(dst), "l"(src) : "memory")
#define CP_COMMIT() asm volatile("cp.async.commit_group;" ::: "memory")
#define CP_WAIT0()  asm volatile("cp.async.wait_group 0;" ::: "memory")
#define CP_WAIT1()  asm volatile("cp.async.wait_group 1;" ::: "memory")

__device__ __forceinline__ uint32_t sw(uint32_t base, int row, int ch) {   // 64B rows
    return base + row * 64 + ((ch ^ ((row >> 1) & 3)) << 4);
}
__device__ __forceinline__ uint32_t sw8(uint32_t base, int row, int ch) {  // 32B rows
    return base + row * 32 + ((ch ^ ((row >> 2) & 1)) << 4);
}

// x -> hi bf16 + hi8/lo8 fp8
__global__ __launch_bounds__(256)
void split_kernel(const float* __restrict__ in, bf16* __restrict__ hi,
                  fp8* __restrict__ hi8, fp8* __restrict__ lo8)
{
    size_t i = ((size_t)blockIdx.x * 256 + threadIdx.x) * 4;
    float4 v = *(const float4*)(in + i);
    bf16 h0, l0, h1, l1, h2, l2, h3, l3;
    split_f32(v.x, h0, l0); split_f32(v.y, h1, l1);
    split_f32(v.z, h2, l2); split_f32(v.w, h3, l3);
    uint32_t hp0 = (uint32_t)__bfloat16_as_ushort(h0) | ((uint32_t)__bfloat16_as_ushort(h1) << 16);
    uint32_t hp1 = (uint32_t)__bfloat16_as_ushort(h2) | ((uint32_t)__bfloat16_as_ushort(h3) << 16);
    *(uint2*)(hi + i) = make_uint2(hp0, hp1);
    *(uint32_t*)(hi8 + i) = pack4_e4m3(__bfloat162float(h0) * S_HI8, __bfloat162float(h1) * S_HI8,
                                       __bfloat162float(h2) * S_HI8, __bfloat162float(h3) * S_HI8);
    *(uint32_t*)(lo8 + i) = pack4_e4m3(__bfloat162float(l0) * S_LO8, __bfloat162float(l1) * S_LO8,
                                       __bfloat162float(l2) * S_LO8, __bfloat162float(l3) * S_LO8);
}

// W -> (32W)^T: hi bf16 + hi8/lo8 fp8
__global__ __launch_bounds__(256)
void wt_split_kernel(const float* __restrict__ W, bf16* __restrict__ Whi,
                     fp8* __restrict__ Whi8, fp8* __restrict__ Wlo8)
{
    __shared__ float tile[32][33];
    int x = blockIdx.x * 32 + threadIdx.x;
    int y = blockIdx.y * 32 + threadIdx.y;
    #pragma unroll
    for (int i = 0; i < 32; i += 8)
        tile[threadIdx.y + i][threadIdx.x] = W[(size_t)(y + i) * DK + x] * 32.0f;
    __syncthreads();
    int x2 = blockIdx.y * 32 + threadIdx.x;
    int y2 = blockIdx.x * 32 + threadIdx.y;
    #pragma unroll
    for (int i = 0; i < 32; i += 8) {
        float v = tile[threadIdx.x][threadIdx.y + i];
        bf16 h, l; split_f32(v, h, l);
        size_t o = (size_t)(y2 + i) * D_MODEL + x2;
        Whi[o]  = h;
        Whi8[o] = (fp8)(pack2_e4m3(__bfloat162float(h) * S_HI8, 0.0f) & 0xFF);
        Wlo8[o] = (fp8)(pack2_e4m3(__bfloat162float(l) * S_LO8, 0.0f) & 0xFF);
    }
}

__global__ __launch_bounds__(256)
void v_transpose_kernel(const bf16* __restrict__ Vhi, const bf16* __restrict__ Vlo,
                        bf16* __restrict__ Vthi, bf16* __restrict__ Vtlo)
{
    __shared__ bf16 th[32][34];
    __shared__ bf16 tl[32][34];
    const size_t in_base  = (size_t)blockIdx.z * SEQ * DK;
    const size_t out_base = (size_t)blockIdx.z * DK * SEQ;
    int n = blockIdx.x * 32 + threadIdx.x;
    int t = blockIdx.y * 32 + threadIdx.y;
    #pragma unroll
    for (int i = 0; i < 32; i += 8) {
        th[threadIdx.y + i][threadIdx.x] = Vhi[in_base + (size_t)(t + i) * DK + n];
        tl[threadIdx.y + i][threadIdx.x] = Vlo[in_base + (size_t)(t + i) * DK + n];
    }
    __syncthreads();
    int t2 = blockIdx.y * 32 + threadIdx.x;
    int n2 = blockIdx.x * 32 + threadIdx.y;
    #pragma unroll
    for (int i = 0; i < 32; i += 8) {
        Vthi[out_base + (size_t)(n2 + i) * SEQ + t2] = th[threadIdx.x][threadIdx.y + i];
        Vtlo[out_base + (size_t)(n2 + i) * SEQ + t2] = tl[threadIdx.x][threadIdx.y + i];
    }
}

// ==== GEMM: 128x128 tile, 256 thr, 2 CTAs/SM, 2-stage cp.async ====
// FP8C=1: acc = Ah@Bh (bf16) + Al8@Bh8 + Ah8@Bl8 (e4m3)
// FP8C=0: acc = Ah@Bh + Al@Bh + Ah@Bl (bf16)
#define STG_B   32768
#define F_AH    0
#define F_BH    8192
#define F_AH8   16384
#define F_AL8   20480
#define F_BH8   24576
#define F_BL8   28672
#define T_A1    16384
#define T_B1    24576
#define GEMM_SMEM (2 * STG_B)

template<int FP8C>
__device__ __forceinline__ void load_stage(uint32_t st,
    const bf16* Ahi, const bf16* Alo, const bf16* Bhi, const bf16* Blo,
    const fp8* Ahi8, const fp8* Alo8, const fp8* Bhi8, const fp8* Blo8,
    int K, int bm, int bn, int k0, int tid)
{
    #pragma unroll
    for (int i = 0; i < 2; i++) {
        const int f = tid + (i << 8);
        const int r = f >> 2;
        const int c = f & 3;
        const uint32_t so = (uint32_t)(r * 64 + ((c ^ ((r >> 1) & 3)) << 4));
        const size_t ga = (size_t)(bm + r) * K + k0 + c * 8;
        const size_t gb = (size_t)(bn + r) * K + k0 + c * 8;
        CP_ASYNC16(st + F_AH + so, Ahi + ga);
        CP_ASYNC16(st + F_BH + so, Bhi + gb);
        if (!FP8C) {
            CP_ASYNC16(st + T_A1 + so, Alo + ga);
            CP_ASYNC16(st + T_B1 + so, Blo + gb);
        }
    }
    if (FP8C) {
        const int r8 = tid >> 1;
        const int c8 = tid & 1;
        const uint32_t so8 = (uint32_t)(r8 * 32 + ((c8 ^ ((r8 >> 2) & 1)) << 4));
        const size_t ga = (size_t)(bm + r8) * K + k0 + c8 * 16;
        const size_t gb = (size_t)(bn + r8) * K + k0 + c8 * 16;
        CP_ASYNC16(st + F_AH8 + so8, Ahi8 + ga);
        CP_ASYNC16(st + F_AL8 + so8, Alo8 + ga);
        CP_ASYNC16(st + F_BH8 + so8, Bhi8 + gb);
        CP_ASYNC16(st + F_BL8 + so8, Blo8 + gb);
    }
}

template<int FP8C>
__global__ __launch_bounds__(256, 2)
void gemm_nt(const bf16* __restrict__ Ahi, const bf16* __restrict__ Alo,
             const bf16* __restrict__ Bhi, const bf16* __restrict__ Blo,
             const fp8* __restrict__ Ahi8, const fp8* __restrict__ Alo8,
             const fp8* __restrict__ Bhi8, const fp8* __restrict__ Blo8,
             int K, size_t sA, size_t sB,
             int mode, float scale, int causal, int trik,
             float* __restrict__ Cf, int ldc, size_t sC,
             bf16* __restrict__ Chi, bf16* __restrict__ Clo,
             fp8* __restrict__ Chi8, fp8* __restrict__ Clo8, size_t sCbf)
{
    const int bm = blockIdx.y * 128;
    const int bn = blockIdx.x * 128;
    const int b  = blockIdx.z;
    if (causal && bn > bm + 127) return;

    Ahi += (size_t)b * sA;  Bhi += (size_t)b * sB;
    if (FP8C) { Ahi8 += (size_t)b * sA; Alo8 += (size_t)b * sA;
                Bhi8 += (size_t)b * sB; Blo8 += (size_t)b * sB; }
    else      { Alo += (size_t)b * sA;  Blo += (size_t)b * sB; }

    extern __shared__ char smem[];
    const uint32_t sb = smem_to_u32(smem);
    const int tid  = threadIdx.x;
    const int lane = tid & 31;
    const int wid  = tid >> 5;
    const int wm   = wid & 3;
    const int wn   = wid >> 2;

    float acc[2][8][4];
    #pragma unroll
    for (int mt = 0; mt < 2; mt++)
        #pragma unroll
        for (int nt = 0; nt < 8; nt++)
            #pragma unroll
            for (int j = 0; j < 4; j++) acc[mt][nt][j] = 0.0f;

    int Keff = trik ? (bm + 128 < K ? bm + 128 : K) : K;
    const int nc = Keff >> 5;

    load_stage<FP8C>(sb, Ahi, Alo, Bhi, Blo, Ahi8, Alo8, Bhi8, Blo8, K, bm, bn, 0, tid);
    CP_COMMIT();

    for (int c = 0; c < nc; c++) {
        if (c + 1 < nc) {
            load_stage<FP8C>(sb + ((c + 1) & 1) * STG_B, Ahi, Alo, Bhi, Blo,
                             Ahi8, Alo8, Bhi8, Blo8, K, bm, bn, (c + 1) << 5, tid);
            CP_COMMIT();
            CP_WAIT1();
        } else {
            CP_WAIT0();
        }
        __syncthreads();
        const uint32_t st = sb + (c & 1) * STG_B;
        const int lrow = lane & 15;

        #pragma unroll
        for (int ks = 0; ks < 2; ks++) {
            const int ch = ks * 2 + (lane >> 4);
            uint32_t ah[2][4], bb[8][2];
            #pragma unroll
            for (int mt = 0; mt < 2; mt++) {
                const int r = wm * 32 + mt * 16 + lrow;
                ldm_x4(ah[mt][0], ah[mt][1], ah[mt][2], ah[mt][3], sw(st + F_AH, r, ch));
            }
            #pragma unroll
            for (int np = 0; np < 4; np++) {
                const int r = wn * 64 + np * 16 + lrow;
                uint32_t r0, r1, r2, r3;
                ldm_x4(r0, r1, r2, r3, sw(st + F_BH, r, ch));
                bb[2*np][0] = r0; bb[2*np+1][0] = r1;
                bb[2*np][1] = r2; bb[2*np+1][1] = r3;
            }
            #pragma unroll
            for (int mt = 0; mt < 2; mt++)
                #pragma unroll
                for (int nt = 0; nt < 8; nt++)
                    mma_bf16(acc[mt][nt], ah[mt], bb[nt]);
            if (!FP8C) {
                uint32_t aw[2][4];
                #pragma unroll
                for (int mt = 0; mt < 2; mt++) {
                    const int r = wm * 32 + mt * 16 + lrow;
                    ldm_x4(aw[mt][0], aw[mt][1], aw[mt][2], aw[mt][3], sw(st + T_A1, r, ch));
                }
                #pragma unroll
                for (int mt = 0; mt < 2; mt++)
                    #pragma unroll
                    for (int nt = 0; nt < 8; nt++)
                        mma_bf16(acc[mt][nt], aw[mt], bb[nt]);
                #pragma unroll
                for (int np = 0; np < 4; np++) {
                    const int r = wn * 64 + np * 16 + lrow;
                    uint32_t r0, r1, r2, r3;
                    ldm_x4(r0, r1, r2, r3, sw(st + T_B1, r, ch));
                    bb[2*np][0] = r0; bb[2*np+1][0] = r1;
                    bb[2*np][1] = r2; bb[2*np+1][1] = r3;
                }
                #pragma unroll
                for (int mt = 0; mt < 2; mt++)
                    #pragma unroll
                    for (int nt = 0; nt < 8; nt++)
                        mma_bf16(acc[mt][nt], ah[mt], bb[nt]);
            }
        }
        if (FP8C) {
            const int ch8 = lane >> 4;
            uint32_t a8[2][4], b8[8][2];
            #pragma unroll
            for (int mt = 0; mt < 2; mt++) {
                const int r = wm * 32 + mt * 16 + lrow;
                ldm_x4(a8[mt][0], a8[mt][1], a8[mt][2], a8[mt][3], sw8(st + F_AL8, r, ch8));
            }
            #pragma unroll
            for (int np = 0; np < 4; np++) {
                const int r = wn * 64 + np * 16 + lrow;
                uint32_t r0, r1, r2, r3;
                ldm_x4(r0, r1, r2, r3, sw8(st + F_BH8, r, ch8));
                b8[2*np][0] = r0; b8[2*np+1][0] = r1;
                b8[2*np][1] = r2; b8[2*np+1][1] = r3;
            }
            #pragma unroll
            for (int mt = 0; mt < 2; mt++)
                #pragma unroll
                for (int nt = 0; nt < 8; nt++)
                    mma_fp8(acc[mt][nt], a8[mt], b8[nt]);
            #pragma unroll
            for (int mt = 0; mt < 2; mt++) {
                const int r = wm * 32 + mt * 16 + lrow;
                ldm_x4(a8[mt][0], a8[mt][1], a8[mt][2], a8[mt][3], sw8(st + F_AH8, r, ch8));
            }
            #pragma unroll
            for (int np = 0; np < 4; np++) {
                const int r = wn * 64 + np * 16 + lrow;
                uint32_t r0, r1, r2, r3;
                ldm_x4(r0, r1, r2, r3, sw8(st + F_BL8, r, ch8));
                b8[2*np][0] = r0; b8[2*np+1][0] = r1;
                b8[2*np][1] = r2; b8[2*np+1][1] = r3;
            }
            #pragma unroll
            for (int mt = 0; mt < 2; mt++)
                #pragma unroll
                for (int nt = 0; nt < 8; nt++)
                    mma_fp8(acc[mt][nt], a8[mt], b8[nt]);
        }
        __syncthreads();
    }

    const int tr = lane >> 2;
    const int tc = (lane & 3) * 2;
    if (mode == 0) {
        float* Cb = Cf + (size_t)b * sC;
        #pragma unroll
        for (int mt = 0; mt < 2; mt++)
            #pragma unroll
            for (int nt = 0; nt < 8; nt++) {
                const int row = bm + wm * 32 + mt * 16 + tr;
                const int col = bn + wn * 64 + nt * 8 + tc;
                *(float2*)&Cb[(size_t)row * ldc + col] =
                    make_float2(acc[mt][nt][0] * scale, acc[mt][nt][1] * scale);
                *(float2*)&Cb[(size_t)(row + 8) * ldc + col] =
                    make_float2(acc[mt][nt][2] * scale, acc[mt][nt][3] * scale);
            }
    } else {
        // FIX (R10 bug): apply batch/z offset to ALL four output arrays
        bf16* Hb  = Chi  + (size_t)b * sCbf;
        bf16* Lb  = Clo  + (size_t)b * sCbf;
        fp8*  Hb8 = Chi8 + (size_t)b * sCbf;
        fp8*  Lb8 = Clo8 + (size_t)b * sCbf;
        #pragma unroll
        for (int mt = 0; mt < 2; mt++)
            #pragma unroll
            for (int nt = 0; nt < 8; nt++) {
                const int row = bm + wm * 32 + mt * 16 + tr;
                const int col = bn + wn * 64 + nt * 8 + tc;
                #pragma unroll
                for (int h = 0; h < 2; h++) {
                    float v0 = acc[mt][nt][2*h + 0] * scale;
                    float v1 = acc[mt][nt][2*h + 1] * scale;
                    bf16 h0, l0, h1, l1;
                    split_f32(v0, h0, l0); split_f32(v1, h1, l1);
                    size_t o = (size_t)(row + 8*h) * ldc + col;
                    *(uint32_t*)&Hb[o] = (uint32_t)__bfloat16_as_ushort(h0) |
                                         ((uint32_t)__bfloat16_as_ushort(h1) << 16);
                    *(uint32_t*)&Lb[o] = (uint32_t)__bfloat16_as_ushort(l0) |
                                         ((uint32_t)__bfloat16_as_ushort(l1) << 16);
                    *(unsigned short*)&Hb8[o] = pack2_e4m3(__bfloat162float(h0) * S_HI8,
                                                           __bfloat162float(h1) * S_HI8);
                    *(unsigned short*)&Lb8[o] = pack2_e4m3(__bfloat162float(l0) * S_LO8,
                                                           __bfloat162float(l1) * S_LO8);
                }
            }
    }
}

__global__ __launch_bounds__(256)
void softmax_causal_kernel()
{
    const int q = blockIdx.x;
    const int b = blockIdx.y;
    const size_t base = ((size_t)b * SEQ + q) * SEQ;
    const float* row = g_S + base;
    const int len  = q + 1;
    const int wlen = ((q >> 7) + 1) << 7;

    const int tid = threadIdx.x, lane = tid & 31, w = tid >> 5;
    __shared__ float red_max[8], red_sum[8], s_m, s_inv;

    float m = -INFINITY;
    for (int j = tid; j < len; j += 256) m = fmaxf(m, row[j]);
    #pragma unroll
    for (int o = 16; o; o >>= 1) m = fmaxf(m, __shfl_xor_sync(0xffffffffu, m, o));
    if (lane == 0) red_max[w] = m;
    __syncthreads();
    if (w == 0) {
        float v = (lane < 8) ? red_max[lane] : -INFINITY;
        #pragma unroll
        for (int o = 4; o; o >>= 1) v = fmaxf(v, __shfl_xor_sync(0xffffffffu, v, o));
        if (lane == 0) s_m = v;
    }
    __syncthreads();
    m = s_m;

    float e[8];
    float s = 0.0f;
    {
        int idx = 0;
        for (int j = tid; j < len; j += 256, idx++) { e[idx] = __expf(row[j] - m); s += e[idx]; }
    }
    #pragma unroll
    for (int o = 16; o; o >>= 1) s += __shfl_xor_sync(0xffffffffu, s, o);
    if (lane == 0) red_sum[w] = s;
    __syncthreads();
    if (w == 0) {
        float v = (lane < 8) ? red_sum[lane] : 0.0f;
        #pragma unroll
        for (int o = 4; o; o >>= 1) v += __shfl_xor_sync(0xffffffffu, v, o);
        if (lane == 0) s_inv = 1.0f / v;
    }
    __syncthreads();
    const float inv = s_inv;

    {
        int idx = 0;
        for (int j = tid; j < wlen; j += 256) {
            float p;
            if (j < len) { p = e[idx] * inv; idx++; } else p = 0.0f;
            bf16 h, l; split_f32(p, h, l);
            g_Phi[base + j] = h;
            g_Plo[base + j] = l;
        }
    }
}

extern "C" void kernel_launch(void* const* d_in, const int* in_sizes, int n_in,
                              void* d_out, int out_size)
{
    const float* x  = (const float*)d_in[0];
    const float* Wq = (const float*)d_in[1];
    const float* Wk = (const float*)d_in[2];
    const float* Wv = (const float*)d_in[3];
    float* out = (float*)d_out;

    cudaFuncSetAttribute(gemm_nt<1>, cudaFuncAttributeMaxDynamicSharedMemorySize, GEMM_SMEM);
    cudaFuncSetAttribute(gemm_nt<0>, cudaFuncAttributeMaxDynamicSharedMemorySize, GEMM_SMEM);

    bf16 *xhi, *wthi, *qkvhi, *qkvlo, *Vthi, *Vtlo, *Phi, *Plo;
    fp8 *xhi8, *xlo8, *wthi8, *wtlo8, *qkvhi8, *qkvlo8;
    float *Sp;
    cudaGetSymbolAddress((void**)&xhi, g_xhi);
    cudaGetSymbolAddress((void**)&xhi8, g_xhi8);   cudaGetSymbolAddress((void**)&xlo8, g_xlo8);
    cudaGetSymbolAddress((void**)&wthi, g_wthi);
    cudaGetSymbolAddress((void**)&wthi8, g_wthi8); cudaGetSymbolAddress((void**)&wtlo8, g_wtlo8);
    cudaGetSymbolAddress((void**)&qkvhi, g_QKVhi); cudaGetSymbolAddress((void**)&qkvlo, g_QKVlo);
    cudaGetSymbolAddress((void**)&qkvhi8, g_QKVhi8); cudaGetSymbolAddress((void**)&qkvlo8, g_QKVlo8);
    cudaGetSymbolAddress((void**)&Vthi, g_Vthi);   cudaGetSymbolAddress((void**)&Vtlo, g_Vtlo);
    cudaGetSymbolAddress((void**)&Phi, g_Phi);     cudaGetSymbolAddress((void**)&Plo, g_Plo);
    cudaGetSymbolAddress((void**)&Sp, g_S);

    const size_t WSZ  = (size_t)D_MODEL * DK;
    const size_t QKVS = (size_t)BT * DK;

    split_kernel<<<(BT * D_MODEL) / (256 * 4), 256>>>(x, xhi, xhi8, xlo8);
    {
        dim3 g(DK / 32, D_MODEL / 32), blk(32, 8);
        wt_split_kernel<<<g, blk>>>(Wq, wthi + 0 * WSZ, wthi8 + 0 * WSZ, wtlo8 + 0 * WSZ);
        wt_split_kernel<<<g, blk>>>(Wk, wthi + 1 * WSZ, wthi8 + 1 * WSZ, wtlo8 + 1 * WSZ);
        wt_split_kernel<<<g, blk>>>(Wv, wthi + 2 * WSZ, wthi8 + 2 * WSZ, wtlo8 + 2 * WSZ);
    }

    // QKV' = x @ (32W): fp8 crosses, outputs bf16 hi/lo + fp8 hi8/lo8
    {
        dim3 grid(DK / 128, BT / 128, 3);
        gemm_nt<1><<<grid, 256, GEMM_SMEM>>>(xhi, nullptr, wthi, nullptr,
            xhi8, xlo8, wthi8, wtlo8,
            D_MODEL, 0, WSZ, 1, 1.0f, 0, 0,
            nullptr, DK, 0, qkvhi, qkvlo, qkvhi8, qkvlo8, QKVS);
    }
    {
        dim3 g(DK / 32, SEQ / 32, BATCH), blk(32, 8);
        v_transpose_kernel<<<g, blk>>>(qkvhi + 2 * QKVS, qkvlo + 2 * QKVS, Vthi, Vtlo);
    }
    // scores = Q'K'^T / 32768, fp8 crosses, causal skip
    {
        dim3 grid(SEQ / 128, SEQ / 128, BATCH);
        gemm_nt<1><<<grid, 256, GEMM_SMEM>>>(qkvhi, nullptr, qkvhi + QKVS, nullptr,
            qkvhi8, qkvlo8, qkvhi8 + QKVS, qkvlo8 + QKVS,
            DK, (size_t)SEQ * DK, (size_t)SEQ * DK, 0, 1.0f / 32768.0f, 1, 0,
            Sp, SEQ, (size_t)SEQ * SEQ, nullptr, nullptr, nullptr, nullptr, 0);
    }
    softmax_causal_kernel<<<dim3(SEQ, BATCH), 256>>>();
    // out = P @ V'/32, bf16 crosses, K truncated
    {
        dim3 grid(DK / 128, SEQ / 128, BATCH);
        gemm_nt<0><<<grid, 256, GEMM_SMEM>>>(Phi, Plo, Vthi, Vtlo,
            nullptr, nullptr, nullptr, nullptr,
            SEQ, (size_t)SEQ * SEQ, (size_t)DK * SEQ, 0, 1.0f / 32.0f, 0, 1,
            out, DK, (size_t)SEQ * DK, nullptr, nullptr, nullptr, nullptr, 0);
    }
}

// round 12
// speedup vs baseline: 1.1283x; 1.1283x over previous
#include <cuda_runtime.h>
#include <cuda_bf16.h>
#include <math.h>
#include <stddef.h>
#include <stdint.h>

#define D_MODEL 1024
#define DK      1024
#define BATCH   4
#define SEQ     2048
#define BT      (BATCH * SEQ)

typedef __nv_bfloat16 bf16;

__device__ bf16 g_xhi[(size_t)BT * D_MODEL];
__device__ bf16 g_xlo[(size_t)BT * D_MODEL];
__device__ bf16 g_wthi[3][(size_t)D_MODEL * DK];
__device__ bf16 g_wtlo[3][(size_t)D_MODEL * DK];
__device__ bf16 g_QKVhi[3][(size_t)BT * DK];
__device__ bf16 g_QKVlo[3][(size_t)BT * DK];
__device__ bf16 g_Vthi[(size_t)BATCH * DK * SEQ];
__device__ bf16 g_Vtlo[(size_t)BATCH * DK * SEQ];
__device__ float g_S[(size_t)BATCH * SEQ * SEQ];
__device__ bf16 g_Phi[(size_t)BATCH * SEQ * SEQ];
__device__ bf16 g_Plo[(size_t)BATCH * SEQ * SEQ];

__device__ __forceinline__ void split_f32(float v, bf16& h, bf16& l) {
    h = __float2bfloat16(v);
    l = __float2bfloat16(v - __bfloat162float(h));
}
__device__ __forceinline__ uint32_t smem_to_u32(const void* p) {
    uint32_t a;
    asm("{ .reg .u64 t; cvta.to.shared.u64 t, %1; cvt.u32.u64 %0, t; }" : "=r"(a) : "l"(p));
    return a;
}
__device__ __forceinline__ void ldm_x4(uint32_t& r0, uint32_t& r1, uint32_t& r2, uint32_t& r3,
                                       uint32_t addr) {
    asm volatile("ldmatrix.sync.aligned.m8n8.x4.shared.b16 {%0,%1,%2,%3}, [%4];"
                 : "=r"(r0), "=r"(r1), "=r"(r2), "=r"(r3) : "r"(addr));
}
__device__ __forceinline__ void mma_bf16(float* c, const uint32_t* a, const uint32_t* b) {
    asm volatile("mma.sync.aligned.m16n8k16.row.col.f32.bf16.bf16.f32 "
                 "{%0,%1,%2,%3}, {%4,%5,%6,%7}, {%8,%9}, {%0,%1,%2,%3};"
                 : "+f"(c[0]), "+f"(c[1]), "+f"(c[2]), "+f"(c[3])
                 : "r"(a[0]), "r"(a[1]), "r"(a[2]), "r"(a[3]), "r"(b[0]), "r"(b[1]));
}

#define CP_ASYNC16(dst, src) \
    asm volatile("cp.async.cg.shared.global [%0], [%1], 16;" :: "r"(dst), "l"(src) : "memory")
#define CP_COMMIT() asm volatile("cp.async.commit_group;" ::: "memory")
#define CP_WAIT0()  asm volatile("cp.async.wait_group 0;" ::: "memory")
#define CP_WAIT1()  asm volatile("cp.async.wait_group 1;" ::: "memory")

__device__ __forceinline__ uint32_t sw(uint32_t base, int row, int ch) {
    return base + row * 64 + ((ch ^ ((row >> 1) & 3)) << 4);
}

// ===========================================================================
__global__ __launch_bounds__(256)
void split_kernel(const float* __restrict__ in, bf16* __restrict__ hi, bf16* __restrict__ lo)
{
    size_t i = ((size_t)blockIdx.x * 256 + threadIdx.x) * 4;
    float4 v = *(const float4*)(in + i);
    bf16 h0, l0, h1, l1, h2, l2, h3, l3;
    split_f32(v.x, h0, l0); split_f32(v.y, h1, l1);
    split_f32(v.z, h2, l2); split_f32(v.w, h3, l3);
    uint32_t hp0 = (uint32_t)__bfloat16_as_ushort(h0) | ((uint32_t)__bfloat16_as_ushort(h1) << 16);
    uint32_t hp1 = (uint32_t)__bfloat16_as_ushort(h2) | ((uint32_t)__bfloat16_as_ushort(h3) << 16);
    uint32_t lp0 = (uint32_t)__bfloat16_as_ushort(l0) | ((uint32_t)__bfloat16_as_ushort(l1) << 16);
    uint32_t lp1 = (uint32_t)__bfloat16_as_ushort(l2) | ((uint32_t)__bfloat16_as_ushort(l3) << 16);
    *(uint2*)(hi + i) = make_uint2(hp0, hp1);
    *(uint2*)(lo + i) = make_uint2(lp0, lp1);
}

__global__ __launch_bounds__(256)
void wt_split_kernel(const float* __restrict__ W, bf16* __restrict__ Whi, bf16* __restrict__ Wlo)
{
    __shared__ float tile[32][33];
    int x = blockIdx.x * 32 + threadIdx.x;
    int y = blockIdx.y * 32 + threadIdx.y;
    #pragma unroll
    for (int i = 0; i < 32; i += 8)
        tile[threadIdx.y + i][threadIdx.x] = W[(size_t)(y + i) * DK + x];
    __syncthreads();
    int x2 = blockIdx.y * 32 + threadIdx.x;
    int y2 = blockIdx.x * 32 + threadIdx.y;
    #pragma unroll
    for (int i = 0; i < 32; i += 8) {
        float v = tile[threadIdx.x][threadIdx.y + i];
        bf16 h, l; split_f32(v, h, l);
        Whi[(size_t)(y2 + i) * D_MODEL + x2] = h;
        Wlo[(size_t)(y2 + i) * D_MODEL + x2] = l;
    }
}

__global__ __launch_bounds__(256)
void v_transpose_kernel(const bf16* __restrict__ Vhi, const bf16* __restrict__ Vlo,
                        bf16* __restrict__ Vthi, bf16* __restrict__ Vtlo)
{
    __shared__ bf16 th[32][34];
    __shared__ bf16 tl[32][34];
    const size_t in_base  = (size_t)blockIdx.z * SEQ * DK;
    const size_t out_base = (size_t)blockIdx.z * DK * SEQ;
    int n = blockIdx.x * 32 + threadIdx.x;
    int t = blockIdx.y * 32 + threadIdx.y;
    #pragma unroll
    for (int i = 0; i < 32; i += 8) {
        th[threadIdx.y + i][threadIdx.x] = Vhi[in_base + (size_t)(t + i) * DK + n];
        tl[threadIdx.y + i][threadIdx.x] = Vlo[in_base + (size_t)(t + i) * DK + n];
    }
    __syncthreads();
    int t2 = blockIdx.y * 32 + threadIdx.x;
    int n2 = blockIdx.x * 32 + threadIdx.y;
    #pragma unroll
    for (int i = 0; i < 32; i += 8) {
        Vthi[out_base + (size_t)(n2 + i) * SEQ + t2] = th[threadIdx.x][threadIdx.y + i];
        Vtlo[out_base + (size_t)(n2 + i) * SEQ + t2] = tl[threadIdx.x][threadIdx.y + i];
    }
}

// ===========================================================================
// HMMA split-bf16 GEMM: 128x128 CTA tile, 128 threads / 4 warps (2Mx2N),
// warp tile 64x64, KC=32, 2-stage cp.async, 2 CTAs/SM.
//   acc = Ah@Bh + Al@Bh + Ah@Bl
// ===========================================================================
#define STG_B   32768
#define T_A0    0
#define T_A1    8192
#define T_B0    16384
#define T_B1    24576
#define GEMM_SMEM (2 * STG_B)

__device__ __forceinline__ void load_stage(uint32_t st,
    const bf16* Ahi, const bf16* Alo, const bf16* Bhi, const bf16* Blo,
    int K, int bm, int bn, int k0, int tid)
{
    #pragma unroll
    for (int i = 0; i < 4; i++) {
        const int f = tid + (i << 7);          // 0..511
        const int r = f >> 2;
        const int c = f & 3;
        const uint32_t so = (uint32_t)(r * 64 + ((c ^ ((r >> 1) & 3)) << 4));
        const size_t ga = (size_t)(bm + r) * K + k0 + c * 8;
        const size_t gb = (size_t)(bn + r) * K + k0 + c * 8;
        CP_ASYNC16(st + T_A0 + so, Ahi + ga);
        CP_ASYNC16(st + T_A1 + so, Alo + ga);
        CP_ASYNC16(st + T_B0 + so, Bhi + gb);
        CP_ASYNC16(st + T_B1 + so, Blo + gb);
    }
}

__global__ __launch_bounds__(128, 2)
void gemm_nt_hmma(const bf16* __restrict__ Ahi, const bf16* __restrict__ Alo,
                  const bf16* __restrict__ Bhi, const bf16* __restrict__ Blo,
                  int K, size_t sA, size_t sB,
                  int mode, float scale, int causal, int trik,
                  float* __restrict__ Cf, int ldc, size_t sC,
                  bf16* __restrict__ Chi, bf16* __restrict__ Clo, size_t sCbf)
{
    const int bm = blockIdx.y * 128;
    const int bn = blockIdx.x * 128;
    const int b  = blockIdx.z;
    if (causal && bn > bm + 127) return;

    Ahi += (size_t)b * sA;  Alo += (size_t)b * sA;
    Bhi += (size_t)b * sB;  Blo += (size_t)b * sB;

    extern __shared__ char smem[];
    const uint32_t sb = smem_to_u32(smem);

    const int tid  = threadIdx.x;
    const int lane = tid & 31;
    const int wid  = tid >> 5;        // 0..3
    const int wm   = wid & 1;         // 0..1 -> 64-row slice
    const int wn   = wid >> 1;        // 0..1 -> 64-col slice

    float acc[4][8][4];
    #pragma unroll
    for (int mt = 0; mt < 4; mt++)
        #pragma unroll
        for (int nt = 0; nt < 8; nt++)
            #pragma unroll
            for (int j = 0; j < 4; j++) acc[mt][nt][j] = 0.0f;

    int Keff = trik ? (bm + 128 < K ? bm + 128 : K) : K;
    const int nc = Keff >> 5;

    load_stage(sb, Ahi, Alo, Bhi, Blo, K, bm, bn, 0, tid);
    CP_COMMIT();

    for (int c = 0; c < nc; c++) {
        if (c + 1 < nc) {
            load_stage(sb + ((c + 1) & 1) * STG_B, Ahi, Alo, Bhi, Blo,
                       K, bm, bn, (c + 1) << 5, tid);
            CP_COMMIT();
            CP_WAIT1();
        } else {
            CP_WAIT0();
        }
        __syncthreads();

        const uint32_t st  = sb + (c & 1) * STG_B;
        const uint32_t aA0 = st + T_A0, aA1 = st + T_A1;
        const uint32_t aB0 = st + T_B0, aB1 = st + T_B1;

        #pragma unroll
        for (int ks = 0; ks < 2; ks++) {
            const int lrow = lane & 15;
            const int ch   = ks * 2 + (lane >> 4);

            uint32_t ah[4][4], aw[4][4], bb[8][2];

            // A_hi fragments: 4 m-tiles
            #pragma unroll
            for (int mt = 0; mt < 4; mt++) {
                const int r = wm * 64 + mt * 16 + lrow;
                ldm_x4(ah[mt][0], ah[mt][1], ah[mt][2], ah[mt][3], sw(aA0, r, ch));
            }
            // B_hi fragments: 64 cols = 4 x4-ldmatrix
            #pragma unroll
            for (int np = 0; np < 4; np++) {
                const int r = wn * 64 + np * 16 + lrow;
                uint32_t r0, r1, r2, r3;
                ldm_x4(r0, r1, r2, r3, sw(aB0, r, ch));
                bb[2*np][0] = r0; bb[2*np+1][0] = r1;
                bb[2*np][1] = r2; bb[2*np+1][1] = r3;
            }
            // pass 1: A_hi @ B_hi
            #pragma unroll
            for (int mt = 0; mt < 4; mt++)
                #pragma unroll
                for (int nt = 0; nt < 8; nt++)
                    mma_bf16(acc[mt][nt], ah[mt], bb[nt]);
            // pass 2: A_lo @ B_hi
            #pragma unroll
            for (int mt = 0; mt < 4; mt++) {
                const int r = wm * 64 + mt * 16 + lrow;
                ldm_x4(aw[mt][0], aw[mt][1], aw[mt][2], aw[mt][3], sw(aA1, r, ch));
            }
            #pragma unroll
            for (int mt = 0; mt < 4; mt++)
                #pragma unroll
                for (int nt = 0; nt < 8; nt++)
                    mma_bf16(acc[mt][nt], aw[mt], bb[nt]);
            // pass 3: A_hi @ B_lo (reuse bb)
            #pragma unroll
            for (int np = 0; np < 4; np++) {
                const int r = wn * 64 + np * 16 + lrow;
                uint32_t r0, r1, r2, r3;
                ldm_x4(r0, r1, r2, r3, sw(aB1, r, ch));
                bb[2*np][0] = r0; bb[2*np+1][0] = r1;
                bb[2*np][1] = r2; bb[2*np+1][1] = r3;
            }
            #pragma unroll
            for (int mt = 0; mt < 4; mt++)
                #pragma unroll
                for (int nt = 0; nt < 8; nt++)
                    mma_bf16(acc[mt][nt], ah[mt], bb[nt]);
        }
        __syncthreads();
    }

    // ---- epilogue ----
    const int tr = lane >> 2;
    const int tc = (lane & 3) * 2;
    if (mode == 0) {
        float* Cb = Cf + (size_t)b * sC;
        #pragma unroll
        for (int mt = 0; mt < 4; mt++)
            #pragma unroll
            for (int nt = 0; nt < 8; nt++) {
                const int row = bm + wm * 64 + mt * 16 + tr;
                const int col = bn + wn * 64 + nt * 8 + tc;
                *(float2*)&Cb[(size_t)row * ldc + col] =
                    make_float2(acc[mt][nt][0] * scale, acc[mt][nt][1] * scale);
                *(float2*)&Cb[(size_t)(row + 8) * ldc + col] =
                    make_float2(acc[mt][nt][2] * scale, acc[mt][nt][3] * scale);
            }
    } else {
        bf16* Hb = Chi + (size_t)b * sCbf;
        bf16* Lb = Clo + (size_t)b * sCbf;
        #pragma unroll
        for (int mt = 0; mt < 4; mt++)
            #pragma unroll
            for (int nt = 0; nt < 8; nt++) {
                const int row = bm + wm * 64 + mt * 16 + tr;
                const int col = bn + wn * 64 + nt * 8 + tc;
                #pragma unroll
                for (int h = 0; h < 2; h++) {
                    float v0 = acc[mt][nt][2*h + 0] * scale;
                    float v1 = acc[mt][nt][2*h + 1] * scale;
                    bf16 h0, l0, h1, l1;
                    split_f32(v0, h0, l0); split_f32(v1, h1, l1);
                    size_t o = (size_t)(row + 8*h) * ldc + col;
                    *(uint32_t*)&Hb[o] = (uint32_t)__bfloat16_as_ushort(h0) |
                                         ((uint32_t)__bfloat16_as_ushort(h1) << 16);
                    *(uint32_t*)&Lb[o] = (uint32_t)__bfloat16_as_ushort(l0) |
                                         ((uint32_t)__bfloat16_as_ushort(l1) << 16);
                }
            }
    }
}

// ===========================================================================
__global__ __launch_bounds__(256)
void softmax_causal_kernel()
{
    const int q = blockIdx.x;
    const int b = blockIdx.y;
    const size_t base = ((size_t)b * SEQ + q) * SEQ;
    const float* row = g_S + base;
    const int len  = q + 1;
    const int wlen = ((q >> 7) + 1) << 7;

    const int tid = threadIdx.x, lane = tid & 31, w = tid >> 5;
    __shared__ float red_max[8], red_sum[8], s_m, s_inv;

    float m = -INFINITY;
    for (int j = tid; j < len; j += 256) m = fmaxf(m, row[j]);
    #pragma unroll
    for (int o = 16; o; o >>= 1) m = fmaxf(m, __shfl_xor_sync(0xffffffffu, m, o));
    if (lane == 0) red_max[w] = m;
    __syncthreads();
    if (w == 0) {
        float v = (lane < 8) ? red_max[lane] : -INFINITY;
        #pragma unroll
        for (int o = 4; o; o >>= 1) v = fmaxf(v, __shfl_xor_sync(0xffffffffu, v, o));
        if (lane == 0) s_m = v;
    }
    __syncthreads();
    m = s_m;

    float e[8];
    float s = 0.0f;
    {
        int idx = 0;
        for (int j = tid; j < len; j += 256, idx++) { e[idx] = __expf(row[j] - m); s += e[idx]; }
    }
    #pragma unroll
    for (int o = 16; o; o >>= 1) s += __shfl_xor_sync(0xffffffffu, s, o);
    if (lane == 0) red_sum[w] = s;
    __syncthreads();
    if (w == 0) {
        float v = (lane < 8) ? red_sum[lane] : 0.0f;
        #pragma unroll
        for (int o = 4; o; o >>= 1) v += __shfl_xor_sync(0xffffffffu, v, o);
        if (lane == 0) s_inv = 1.0f / v;
    }
    __syncthreads();
    const float inv = s_inv;

    {
        int idx = 0;
        for (int j = tid; j < wlen; j += 256) {
            float p;
            if (j < len) { p = e[idx] * inv; idx++; } else p = 0.0f;
            bf16 h, l; split_f32(p, h, l);
            g_Phi[base + j] = h;
            g_Plo[base + j] = l;
        }
    }
}

// ===========================================================================
extern "C" void kernel_launch(void* const* d_in, const int* in_sizes, int n_in,
                              void* d_out, int out_size)
{
    const float* x  = (const float*)d_in[0];
    const float* Wq = (const float*)d_in[1];
    const float* Wk = (const float*)d_in[2];
    const float* Wv = (const float*)d_in[3];
    float* out = (float*)d_out;

    cudaFuncSetAttribute(gemm_nt_hmma, cudaFuncAttributeMaxDynamicSharedMemorySize, GEMM_SMEM);

    bf16 *xhi, *xlo, *wthi, *wtlo, *qkvhi, *qkvlo, *Vthi, *Vtlo, *Phi, *Plo;
    float *Sp;
    cudaGetSymbolAddress((void**)&xhi, g_xhi);    cudaGetSymbolAddress((void**)&xlo, g_xlo);
    cudaGetSymbolAddress((void**)&wthi, g_wthi);  cudaGetSymbolAddress((void**)&wtlo, g_wtlo);
    cudaGetSymbolAddress((void**)&qkvhi, g_QKVhi); cudaGetSymbolAddress((void**)&qkvlo, g_QKVlo);
    cudaGetSymbolAddress((void**)&Vthi, g_Vthi);  cudaGetSymbolAddress((void**)&Vtlo, g_Vtlo);
    cudaGetSymbolAddress((void**)&Phi, g_Phi);    cudaGetSymbolAddress((void**)&Plo, g_Plo);
    cudaGetSymbolAddress((void**)&Sp, g_S);

    const size_t WSZ  = (size_t)D_MODEL * DK;
    const size_t QKVS = (size_t)BT * DK;

    split_kernel<<<(BT * D_MODEL) / (256 * 4), 256>>>(x, xhi, xlo);
    {
        dim3 g(DK / 32, D_MODEL / 32), blk(32, 8);
        wt_split_kernel<<<g, blk>>>(Wq, wthi + 0 * WSZ, wtlo + 0 * WSZ);
        wt_split_kernel<<<g, blk>>>(Wk, wthi + 1 * WSZ, wtlo + 1 * WSZ);
        wt_split_kernel<<<g, blk>>>(Wv, wthi + 2 * WSZ, wtlo + 2 * WSZ);
    }

    // merged QKV projection
    {
        dim3 grid(DK / 128, BT / 128, 3);
        gemm_nt_hmma<<<grid, 128, GEMM_SMEM>>>(xhi, xlo, wthi, wtlo,
            D_MODEL, 0, WSZ, 1, 1.0f, 0, 0,
            nullptr, DK, 0, qkvhi, qkvlo, QKVS);
    }
    {
        dim3 g(DK / 32, SEQ / 32, BATCH), blk(32, 8);
        v_transpose_kernel<<<g, blk>>>(qkvhi + 2 * QKVS, qkvlo + 2 * QKVS, Vthi, Vtlo);
    }
    // scores = (1/32) Q @ K^T, causal skip
    {
        dim3 grid(SEQ / 128, SEQ / 128, BATCH);
        gemm_nt_hmma<<<grid, 128, GEMM_SMEM>>>(qkvhi, qkvlo, qkvhi + QKVS, qkvlo + QKVS,
            DK, (size_t)SEQ * DK, (size_t)SEQ * DK, 0, 1.0f / 32.0f, 1, 0,
            Sp, SEQ, (size_t)SEQ * SEQ, nullptr, nullptr, 0);
    }
    softmax_causal_kernel<<<dim3(SEQ, BATCH), 256>>>();
    // out = P @ V, K truncated
    {
        dim3 grid(DK / 128, SEQ / 128, BATCH);
        gemm_nt_hmma<<<grid, 128, GEMM_SMEM>>>(Phi, Plo, Vthi, Vtlo,
            SEQ, (size_t)SEQ * SEQ, (size_t)DK * SEQ, 0, 1.0f, 0, 1,
            out, DK, (size_t)SEQ * DK, nullptr, nullptr, 0);
    }
}

// round 14
// speedup vs baseline: 1.8588x; 1.6474x over previous
#include <cuda_runtime.h>
#include <cuda_bf16.h>
#include <math.h>
#include <stddef.h>
#include <stdint.h>

#define D_MODEL 1024
#define DK      1024
#define BATCH   4
#define SEQ     2048
#define BT      (BATCH * SEQ)

// ===========================================================================
// Scratch (f32 everywhere; operands pre-rounded to tf32 bit pattern)
// ===========================================================================
__device__ float g_xt[(size_t)BT * D_MODEL];
__device__ float g_wt[3][(size_t)D_MODEL * DK];     // W^T (dk, d_model), tf32-rounded
__device__ float g_QKV[3][(size_t)BT * DK];         // tf32-rounded Q, K, V
__device__ float g_Vt[(size_t)BATCH * DK * SEQ];    // per batch (dk, t), tf32-rounded
__device__ float g_S[(size_t)BATCH * SEQ * SEQ];    // scores, then P (tf32-rounded)

__device__ __forceinline__ uint32_t smem_to_u32(const void* p) {
    uint32_t a;
    asm("{ .reg .u64 t; cvta.to.shared.u64 t, %1; cvt.u32.u64 %0, t; }" : "=r"(a) : "l"(p));
    return a;
}
__device__ __forceinline__ float round_tf32(float f) {
    uint32_t r;
    asm("cvt.rna.tf32.f32 %0, %1;" : "=r"(r) : "f"(f));
    return __uint_as_float(r);
}
// m16n8k8 tf32 MMA, fp32 accum
__device__ __forceinline__ void mma_tf32(float* c, const uint32_t* a, const uint32_t* b) {
    asm volatile("mma.sync.aligned.m16n8k8.row.col.f32.tf32.tf32.f32 "
                 "{%0,%1,%2,%3}, {%4,%5,%6,%7}, {%8,%9}, {%0,%1,%2,%3};"
                 : "+f"(c[0]), "+f"(c[1]), "+f"(c[2]), "+f"(c[3])
                 : "r"(a[0]), "r"(a[1]), "r"(a[2]), "r"(a[3]), "r"(b[0]), "r"(b[1]));
}

#define CP_ASYNC16(dst, src) \
    asm volatile("cp.async.cg.shared.global [%0], [%1], 16;" :: "r"(dst), "l"(src) : "memory")
#define CP_COMMIT() asm volatile("cp.async.commit_group;" ::: "memory")
#define CP_WAIT0()  asm volatile("cp.async.wait_group 0;" ::: "memory")
#define CP_WAIT1()  asm volatile("cp.async.wait_group 1;" ::: "memory")

// f32 tile: 128 rows x 32 cols (128B rows = 8 x 16B chunks).
// Write swizzle: chunk' = chunk ^ (row & 7).  BYTE OFFSET for (row, col):
__device__ __forceinline__ uint32_t swf_off(int row, int col) {
    return (uint32_t)(row * 128 + ((((col) >> 2) ^ (row & 7)) << 4) + ((col) & 3) * 4);
}

// ===========================================================================
// x (f32) -> tf32-rounded copy
// ===========================================================================
__global__ __launch_bounds__(256)
void round_kernel(const float* __restrict__ in, float* __restrict__ out)
{
    size_t i = ((size_t)blockIdx.x * 256 + threadIdx.x) * 4;
    float4 v = *(const float4*)(in + i);
    v.x = round_tf32(v.x); v.y = round_tf32(v.y);
    v.z = round_tf32(v.z); v.w = round_tf32(v.w);
    *(float4*)(out + i) = v;
}

// W (d_model, dk) -> W^T (dk, d_model), tf32-rounded
__global__ __launch_bounds__(256)
void wt_round_kernel(const float* __restrict__ W, float* __restrict__ Wt)
{
    __shared__ float tile[32][33];
    int x = blockIdx.x * 32 + threadIdx.x;
    int y = blockIdx.y * 32 + threadIdx.y;
    #pragma unroll
    for (int i = 0; i < 32; i += 8)
        tile[threadIdx.y + i][threadIdx.x] = W[(size_t)(y + i) * DK + x];
    __syncthreads();
    int x2 = blockIdx.y * 32 + threadIdx.x;
    int y2 = blockIdx.x * 32 + threadIdx.y;
    #pragma unroll
    for (int i = 0; i < 32; i += 8)
        Wt[(size_t)(y2 + i) * D_MODEL + x2] = round_tf32(tile[threadIdx.x][threadIdx.y + i]);
}

// V (t, dk) -> V^T (dk, t) per batch (values already rounded)
__global__ __launch_bounds__(256)
void v_transpose_kernel(const float* __restrict__ V, float* __restrict__ Vt)
{
    __shared__ float tile[32][33];
    const size_t in_base  = (size_t)blockIdx.z * SEQ * DK;
    const size_t out_base = (size_t)blockIdx.z * DK * SEQ;
    int n = blockIdx.x * 32 + threadIdx.x;
    int t = blockIdx.y * 32 + threadIdx.y;
    #pragma unroll
    for (int i = 0; i < 32; i += 8)
        tile[threadIdx.y + i][threadIdx.x] = V[in_base + (size_t)(t + i) * DK + n];
    __syncthreads();
    int t2 = blockIdx.y * 32 + threadIdx.x;
    int n2 = blockIdx.x * 32 + threadIdx.y;
    #pragma unroll
    for (int i = 0; i < 32; i += 8)
        Vt[out_base + (size_t)(n2 + i) * SEQ + t2] = tile[threadIdx.x][threadIdx.y + i];
}

// ===========================================================================
// tf32 GEMM: C[M,N] = scale * (A @ B^T)  (A: M x K row-major, B: N x K row-major)
// 128x128 CTA tile, 256 threads, 8 warps (4xM, 2xN), warp tile 32x64,
// KC=32, 2-stage cp.async, 2 CTAs/SM.
// mode 0: C = f32 * scale;  mode 1: C = tf32-rounded (f32 * scale)
// causal: skip CTA if bn > bm+127;  trik: K limited to bm+128.
// ===========================================================================
#define STG_B   32768   // A 16KB + B 16KB per stage
#define T_B     16384
#define GEMM_SMEM (2 * STG_B)

__device__ __forceinline__ void load_stage(uint32_t st,
    const float* A, const float* B, int K, int bm, int bn, int k0, int tid)
{
    #pragma unroll
    for (int i = 0; i < 4; i++) {
        const int f  = tid + (i << 8);      // 0..1023
        const int r  = f >> 3;              // row 0..127
        const int ch = f & 7;               // 16B chunk 0..7
        const uint32_t so = (uint32_t)(r * 128 + ((ch ^ (r & 7)) << 4));
        CP_ASYNC16(st + so,       A + (size_t)(bm + r) * K + k0 + ch * 4);
        CP_ASYNC16(st + T_B + so, B + (size_t)(bn + r) * K + k0 + ch * 4);
    }
}

__global__ __launch_bounds__(256, 2)
void gemm_tf32(const float* __restrict__ A, const float* __restrict__ B,
               int K, size_t sA, size_t sB,
               int mode, float scale, int causal, int trik,
               float* __restrict__ C, int ldc, size_t sC)
{
    const int bm = blockIdx.y * 128;
    const int bn = blockIdx.x * 128;
    const int b  = blockIdx.z;
    if (causal && bn > bm + 127) return;

    A += (size_t)b * sA;
    B += (size_t)b * sB;

    extern __shared__ char smem[];
    const uint32_t sb = smem_to_u32(smem);

    const int tid  = threadIdx.x;
    const int lane = tid & 31;
    const int wid  = tid >> 5;
    const int wm   = wid & 3;        // 0..3 -> 32-row slice
    const int wn   = wid >> 2;       // 0..1 -> 64-col slice
    const int r4   = lane >> 2;      // 0..7
    const int c4   = lane & 3;       // 0..3

    float acc[2][8][4];
    #pragma unroll
    for (int mt = 0; mt < 2; mt++)
        #pragma unroll
        for (int nt = 0; nt < 8; nt++)
            #pragma unroll
            for (int j = 0; j < 4; j++) acc[mt][nt][j] = 0.0f;

    int Keff = trik ? (bm + 128 < K ? bm + 128 : K) : K;
    const int nc = Keff >> 5;

    load_stage(sb, A, B, K, bm, bn, 0, tid);
    CP_COMMIT();

    for (int c = 0; c < nc; c++) {
        if (c + 1 < nc) {
            load_stage(sb + ((c + 1) & 1) * STG_B, A, B, K, bm, bn, (c + 1) << 5, tid);
            CP_COMMIT();
            CP_WAIT1();
        } else {
            CP_WAIT0();
        }
        __syncthreads();

        // generic pointers for LDS fragment loads
        const char* pA = smem + (c & 1) * STG_B;
        const char* pB = pA + T_B;

        #pragma unroll
        for (int ks = 0; ks < 4; ks++) {
            const int col1 = ks * 8 + c4;      // k col for a0/a1/b0
            const int col2 = col1 + 4;         // k col for a2/a3/b1

            uint32_t af[2][4], bf[8][2];
            // A fragments: 2 m-tiles
            #pragma unroll
            for (int mt = 0; mt < 2; mt++) {
                const int row = wm * 32 + mt * 16 + r4;
                af[mt][0] = *(const uint32_t*)(pA + swf_off(row,     col1));
                af[mt][1] = *(const uint32_t*)(pA + swf_off(row + 8, col1));
                af[mt][2] = *(const uint32_t*)(pA + swf_off(row,     col2));
                af[mt][3] = *(const uint32_t*)(pA + swf_off(row + 8, col2));
            }
            // B fragments: 8 n-tiles
            #pragma unroll
            for (int nt = 0; nt < 8; nt++) {
                const int rn = wn * 64 + nt * 8 + r4;
                bf[nt][0] = *(const uint32_t*)(pB + swf_off(rn, col1));
                bf[nt][1] = *(const uint32_t*)(pB + swf_off(rn, col2));
            }
            #pragma unroll
            for (int mt = 0; mt < 2; mt++)
                #pragma unroll
                for (int nt = 0; nt < 8; nt++)
                    mma_tf32(acc[mt][nt], af[mt], bf[nt]);
        }
        __syncthreads();
    }

    // ---- epilogue ----
    const int tr = lane >> 2;
    const int tc = (lane & 3) * 2;
    float* Cb = C + (size_t)b * sC;
    #pragma unroll
    for (int mt = 0; mt < 2; mt++)
        #pragma unroll
        for (int nt = 0; nt < 8; nt++) {
            const int row = bm + wm * 32 + mt * 16 + tr;
            const int col = bn + wn * 64 + nt * 8 + tc;
            float v0 = acc[mt][nt][0] * scale, v1 = acc[mt][nt][1] * scale;
            float v2 = acc[mt][nt][2] * scale, v3 = acc[mt][nt][3] * scale;
            if (mode == 1) {
                v0 = round_tf32(v0); v1 = round_tf32(v1);
                v2 = round_tf32(v2); v3 = round_tf32(v3);
            }
            *(float2*)&Cb[(size_t)row * ldc + col]       = make_float2(v0, v1);
            *(float2*)&Cb[(size_t)(row + 8) * ldc + col] = make_float2(v2, v3);
        }
}

// ===========================================================================
// Causal softmax: in-place on g_S; writes tf32-rounded P, zero tail to
// the 128-aligned PV read boundary.
// ===========================================================================
__global__ __launch_bounds__(256)
void softmax_causal_kernel()
{
    const int q = blockIdx.x;
    const int b = blockIdx.y;
    const size_t base = ((size_t)b * SEQ + q) * SEQ;
    float* row = g_S + base;
    const int len  = q + 1;
    const int wlen = ((q >> 7) + 1) << 7;

    const int tid = threadIdx.x, lane = tid & 31, w = tid >> 5;
    __shared__ float red_max[8], red_sum[8], s_m, s_inv;

    float m = -INFINITY;
    for (int j = tid; j < len; j += 256) m = fmaxf(m, row[j]);
    #pragma unroll
    for (int o = 16; o; o >>= 1) m = fmaxf(m, __shfl_xor_sync(0xffffffffu, m, o));
    if (lane == 0) red_max[w] = m;
    __syncthreads();
    if (w == 0) {
        float v = (lane < 8) ? red_max[lane] : -INFINITY;
        #pragma unroll
        for (int o = 4; o; o >>= 1) v = fmaxf(v, __shfl_xor_sync(0xffffffffu, v, o));
        if (lane == 0) s_m = v;
    }
    __syncthreads();
    m = s_m;

    float e[8];
    float s = 0.0f;
    {
        int idx = 0;
        for (int j = tid; j < len; j += 256, idx++) { e[idx] = __expf(row[j] - m); s += e[idx]; }
    }
    #pragma unroll
    for (int o = 16; o; o >>= 1) s += __shfl_xor_sync(0xffffffffu, s, o);
    if (lane == 0) red_sum[w] = s;
    __syncthreads();
    if (w == 0) {
        float v = (lane < 8) ? red_sum[lane] : 0.0f;
        #pragma unroll
        for (int o = 4; o; o >>= 1) v += __shfl_xor_sync(0xffffffffu, v, o);
        if (lane == 0) s_inv = 1.0f / v;
    }
    __syncthreads();
    const float inv = s_inv;

    {
        int idx = 0;
        for (int j = tid; j < wlen; j += 256) {
            float p;
            if (j < len) { p = round_tf32(e[idx] * inv); idx++; } else p = 0.0f;
            row[j] = p;
        }
    }
}

// ===========================================================================
extern "C" void kernel_launch(void* const* d_in, const int* in_sizes, int n_in,
                              void* d_out, int out_size)
{
    const float* x  = (const float*)d_in[0];
    const float* Wq = (const float*)d_in[1];
    const float* Wk = (const float*)d_in[2];
    const float* Wv = (const float*)d_in[3];
    float* out = (float*)d_out;

    cudaFuncSetAttribute(gemm_tf32, cudaFuncAttributeMaxDynamicSharedMemorySize, GEMM_SMEM);

    float *xt, *wt, *qkv, *Vt, *Sp;
    cudaGetSymbolAddress((void**)&xt, g_xt);
    cudaGetSymbolAddress((void**)&wt, g_wt);
    cudaGetSymbolAddress((void**)&qkv, g_QKV);
    cudaGetSymbolAddress((void**)&Vt, g_Vt);
    cudaGetSymbolAddress((void**)&Sp, g_S);

    const size_t WSZ  = (size_t)D_MODEL * DK;
    const size_t QKVS = (size_t)BT * DK;

    // 1) round x to tf32; W -> W^T rounded
    round_kernel<<<(BT * D_MODEL) / (256 * 4), 256>>>(x, xt);
    {
        dim3 g(DK / 32, D_MODEL / 32), blk(32, 8);
        wt_round_kernel<<<g, blk>>>(Wq, wt + 0 * WSZ);
        wt_round_kernel<<<g, blk>>>(Wk, wt + 1 * WSZ);
        wt_round_kernel<<<g, blk>>>(Wv, wt + 2 * WSZ);
    }

    // 2) merged QKV projection (z selects W and output slice), tf32-rounded out
    {
        dim3 grid(DK / 128, BT / 128, 3);
        gemm_tf32<<<grid, 256, GEMM_SMEM>>>(xt, wt,
            D_MODEL, 0, WSZ, 1, 1.0f, 0, 0,
            qkv, DK, QKVS);
    }

    // 3) V^T per batch
    {
        dim3 g(DK / 32, SEQ / 32, BATCH), blk(32, 8);
        v_transpose_kernel<<<g, blk>>>(qkv + 2 * QKVS, Vt);
    }

    // 4) scores = (1/32) Q @ K^T, causal skip
    {
        dim3 grid(SEQ / 128, SEQ / 128, BATCH);
        gemm_tf32<<<grid, 256, GEMM_SMEM>>>(qkv, qkv + QKVS,
            DK, (size_t)SEQ * DK, (size_t)SEQ * DK, 0, 1.0f / 32.0f, 1, 0,
            Sp, SEQ, (size_t)SEQ * SEQ);
    }

    // 5) causal softmax (in-place, tf32-rounded P)
    softmax_causal_kernel<<<dim3(SEQ, BATCH), 256>>>();

    // 6) out = P @ V (K truncated per diagonal)
    {
        dim3 grid(DK / 128, SEQ / 128, BATCH);
        gemm_tf32<<<grid, 256, GEMM_SMEM>>>(Sp, Vt,
            SEQ, (size_t)SEQ * SEQ, (size_t)DK * SEQ, 0, 1.0f, 0, 1,
            out, DK, (size_t)SEQ * DK);
    }
}